// round 1
// baseline (speedup 1.0000x reference)
#include <cuda_runtime.h>
#include <math.h>

#define BB 8
#define NN 2048
#define FIN 256
#define FOUT 128
#define ALPHA 0.2f
#define CUTOFF 0.1f
#define NEGINF -9e15f

#define QT 64
#define KT 64
#define PSS 68   // p-tile row stride (floats), float4-aligned, conflict-breaking

// Scratch (no cudaMalloc allowed)
__device__ float g_h[BB * NN * FOUT];   // 8 MB
__device__ float g_fs[BB * NN];
__device__ float g_fd[BB * NN];

// ---------------------------------------------------------------------------
// Kernel 1: h = x @ W  (M=16384, K=256, N=128), fused f_src = h@a[:128],
// f_dst = h@a[128:]. Tile 64 rows x 128 cols per block, 256 threads.
// ---------------------------------------------------------------------------
__global__ __launch_bounds__(256, 2)
void gemm_h_kernel(const float* __restrict__ x, const float* __restrict__ W,
                   const float* __restrict__ a) {
    __shared__ float xs[64 * 33];     // padded stride 33
    __shared__ float ws[32 * 128];

    const int t  = threadIdx.x;
    const int tx = t & 31;            // col group: cols tx*4..tx*4+3
    const int ty = t >> 5;            // row group: rows ty*8..ty*8+7
    const int row0 = blockIdx.x * 64;

    float acc[8][4];
#pragma unroll
    for (int i = 0; i < 8; i++)
#pragma unroll
        for (int j = 0; j < 4; j++) acc[i][j] = 0.f;

    for (int k0 = 0; k0 < FIN; k0 += 32) {
        // load x tile: 64 rows x 32 k, coalesced (one row per warp-load)
#pragma unroll
        for (int e = 0; e < 8; e++) {
            int idx = t + e * 256;
            int r = idx >> 5, c = idx & 31;
            xs[r * 33 + c] = x[(size_t)(row0 + r) * FIN + k0 + c];
        }
        // load W tile: 32 k x 128 cols, float4 coalesced
#pragma unroll
        for (int e = 0; e < 4; e++) {
            int vidx = t + e * 256;
            int kk = vidx >> 5, cv = vidx & 31;
            ((float4*)ws)[kk * 32 + cv] =
                ((const float4*)W)[(size_t)(k0 + kk) * 32 + cv];
        }
        __syncthreads();
#pragma unroll
        for (int kk = 0; kk < 32; kk++) {
            float4 wv = ((float4*)ws)[kk * 32 + tx];
#pragma unroll
            for (int i = 0; i < 8; i++) {
                float xv = xs[(ty * 8 + i) * 33 + kk];
                acc[i][0] += xv * wv.x;
                acc[i][1] += xv * wv.y;
                acc[i][2] += xv * wv.z;
                acc[i][3] += xv * wv.w;
            }
        }
        __syncthreads();
    }

    // epilogue: store h, compute f_src / f_dst (warp owns a row)
    const float4 avs = ((const float4*)a)[tx];        // a[0:128]
    const float4 avd = ((const float4*)a)[32 + tx];   // a[128:256]
#pragma unroll
    for (int i = 0; i < 8; i++) {
        int row = row0 + ty * 8 + i;
        float4 v = make_float4(acc[i][0], acc[i][1], acc[i][2], acc[i][3]);
        ((float4*)g_h)[(size_t)row * 32 + tx] = v;
        float ps = v.x * avs.x + v.y * avs.y + v.z * avs.z + v.w * avs.w;
        float pd = v.x * avd.x + v.y * avd.y + v.z * avd.z + v.w * avd.w;
#pragma unroll
        for (int o = 16; o > 0; o >>= 1) {
            ps += __shfl_xor_sync(0xffffffffu, ps, o);
            pd += __shfl_xor_sync(0xffffffffu, pd, o);
        }
        if (tx == 0) { g_fs[row] = ps; g_fd[row] = pd; }
    }
}

// ---------------------------------------------------------------------------
// Kernel 2: fused distance-gated attention + softmax + P@H + ELU.
// Block: 64 queries, 256 threads. Thread = (trow = t/16, tcol = t%16):
//   rows trow*4+{0..3}, cols {tcol*4+0..3} and {64+tcol*4+0..3}.
// Flash-style online softmax over key tiles of 64.
// ---------------------------------------------------------------------------
extern __shared__ float s_dyn[];

__global__ __launch_bounds__(256, 2)
void attn_kernel(const float* __restrict__ coord, float* __restrict__ out) {
    float* hk  = s_dyn;                 // KT*FOUT = 8192 floats
    float* ps  = hk + KT * FOUT;        // QT*PSS  = 4352 floats
    float* ck  = ps + QT * PSS;         // KT*4
    float* fdk = ck + KT * 4;           // KT

    const int t    = threadIdx.x;
    const int tcol = t & 15;
    const int trow = t >> 4;
    const int b    = blockIdx.x >> 5;   // NN/QT = 32 q-tiles per batch
    const int q0   = (blockIdx.x & 31) * QT;

    // per-thread query-side state
    float fs[4], cix[4], ciy[4], ciz[4];
#pragma unroll
    for (int i = 0; i < 4; i++) {
        int q = q0 + trow * 4 + i;
        fs[i] = g_fs[b * NN + q];
        const float* cp = coord + ((size_t)b * NN + q) * 3;
        cix[i] = cp[0]; ciy[i] = cp[1]; ciz[i] = cp[2];
    }
    float m[4], l[4];
    float4 acc0[4], acc1[4];
#pragma unroll
    for (int i = 0; i < 4; i++) {
        m[i] = -INFINITY; l[i] = 0.f;
        acc0[i] = make_float4(0.f, 0.f, 0.f, 0.f);
        acc1[i] = make_float4(0.f, 0.f, 0.f, 0.f);
    }

    for (int k0 = 0; k0 < NN; k0 += KT) {
        __syncthreads();   // previous accumulate done before smem overwrite
        // load key-tile h (coalesced float4)
        const float4* hsrc = (const float4*)(g_h + ((size_t)b * NN + k0) * FOUT);
#pragma unroll
        for (int e = 0; e < 8; e++)
            ((float4*)hk)[t + e * 256] = hsrc[t + e * 256];
        // key coords + f_dst
        if (t < KT) {
            const float* cp = coord + ((size_t)b * NN + k0 + t) * 3;
            ck[t * 4 + 0] = cp[0];
            ck[t * 4 + 1] = cp[1];
            ck[t * 4 + 2] = cp[2];
            fdk[t] = g_fd[b * NN + k0 + t];
        }
        __syncthreads();

        // ---- logits: 4 rows x 4 keys per thread (keys j = tcol*4 + jj) ----
        float lg[4][4];
        float mt[4] = {-INFINITY, -INFINITY, -INFINITY, -INFINITY};
#pragma unroll
        for (int jj = 0; jj < 4; jj++) {
            int j = tcol * 4 + jj;
            float cjx = ck[j * 4], cjy = ck[j * 4 + 1], cjz = ck[j * 4 + 2];
            float fd = fdk[j];
#pragma unroll
            for (int i = 0; i < 4; i++) {
                float dx = cix[i] - cjx, dy = ciy[i] - cjy, dz = ciz[i] - cjz;
                float d2 = dx * dx + dy * dy + dz * dz;
                float loc = __expf(-CUTOFF * d2);
                float e = fs[i] + fd;
                e = e > 0.f ? e : ALPHA * e;
                float v = (loc > 0.01f) ? e * loc : NEGINF;
                lg[i][jj] = v;
                mt[i] = fmaxf(mt[i], v);
            }
        }
        // row max across the 16 lanes owning this row-group
#pragma unroll
        for (int o = 1; o < 16; o <<= 1)
#pragma unroll
            for (int i = 0; i < 4; i++)
                mt[i] = fmaxf(mt[i], __shfl_xor_sync(0xffffffffu, mt[i], o));

        float sc[4], sm[4];
#pragma unroll
        for (int i = 0; i < 4; i++) {
            float mn = fmaxf(m[i], mt[i]);
            sc[i] = __expf(m[i] - mn);   // m=-inf first tile -> exp(-inf)=0
            m[i] = mn;
        }
        // p values, local row sums, store to smem p-tile
#pragma unroll
        for (int i = 0; i < 4; i++) {
            float4 p;
            p.x = __expf(lg[i][0] - m[i]);
            p.y = __expf(lg[i][1] - m[i]);
            p.z = __expf(lg[i][2] - m[i]);
            p.w = __expf(lg[i][3] - m[i]);
            sm[i] = p.x + p.y + p.z + p.w;
            *((float4*)(ps + (trow * 4 + i) * PSS + tcol * 4)) = p;
        }
#pragma unroll
        for (int o = 1; o < 16; o <<= 1)
#pragma unroll
            for (int i = 0; i < 4; i++)
                sm[i] += __shfl_xor_sync(0xffffffffu, sm[i], o);
#pragma unroll
        for (int i = 0; i < 4; i++) {
            l[i] = l[i] * sc[i] + sm[i];
            acc0[i].x *= sc[i]; acc0[i].y *= sc[i];
            acc0[i].z *= sc[i]; acc0[i].w *= sc[i];
            acc1[i].x *= sc[i]; acc1[i].y *= sc[i];
            acc1[i].z *= sc[i]; acc1[i].w *= sc[i];
        }
        __syncwarp();   // p-tile rows are produced/consumed within one warp

        // ---- accumulate: acc += p * hk  (j unrolled x4, float4 p loads) ----
#pragma unroll 2
        for (int j0 = 0; j0 < KT; j0 += 4) {
            float pv[4][4];
#pragma unroll
            for (int i = 0; i < 4; i++) {
                float4 p4 = *((const float4*)(ps + (trow * 4 + i) * PSS + j0));
                pv[i][0] = p4.x; pv[i][1] = p4.y; pv[i][2] = p4.z; pv[i][3] = p4.w;
            }
#pragma unroll
            for (int jj = 0; jj < 4; jj++) {
                float4 h0 = ((const float4*)hk)[(j0 + jj) * 32 + tcol];
                float4 h1 = ((const float4*)hk)[(j0 + jj) * 32 + 16 + tcol];
#pragma unroll
                for (int i = 0; i < 4; i++) {
                    float p = pv[i][jj];
                    acc0[i].x += p * h0.x; acc0[i].y += p * h0.y;
                    acc0[i].z += p * h0.z; acc0[i].w += p * h0.w;
                    acc1[i].x += p * h1.x; acc1[i].y += p * h1.y;
                    acc1[i].z += p * h1.z; acc1[i].w += p * h1.w;
                }
            }
        }
    }

    // ---- epilogue: normalize, ELU, store ----
#pragma unroll
    for (int i = 0; i < 4; i++) {
        int q = q0 + trow * 4 + i;
        float inv = 1.f / l[i];
        float4 o0, o1;
        o0.x = acc0[i].x * inv; o0.y = acc0[i].y * inv;
        o0.z = acc0[i].z * inv; o0.w = acc0[i].w * inv;
        o1.x = acc1[i].x * inv; o1.y = acc1[i].y * inv;
        o1.z = acc1[i].z * inv; o1.w = acc1[i].w * inv;
        o0.x = o0.x > 0.f ? o0.x : (__expf(o0.x) - 1.f);
        o0.y = o0.y > 0.f ? o0.y : (__expf(o0.y) - 1.f);
        o0.z = o0.z > 0.f ? o0.z : (__expf(o0.z) - 1.f);
        o0.w = o0.w > 0.f ? o0.w : (__expf(o0.w) - 1.f);
        o1.x = o1.x > 0.f ? o1.x : (__expf(o1.x) - 1.f);
        o1.y = o1.y > 0.f ? o1.y : (__expf(o1.y) - 1.f);
        o1.z = o1.z > 0.f ? o1.z : (__expf(o1.z) - 1.f);
        o1.w = o1.w > 0.f ? o1.w : (__expf(o1.w) - 1.f);
        float4* op = (float4*)(out + ((size_t)b * NN + q) * FOUT);
        op[tcol]      = o0;
        op[16 + tcol] = o1;
    }
}

// ---------------------------------------------------------------------------
extern "C" void kernel_launch(void* const* d_in, const int* in_sizes, int n_in,
                              void* d_out, int out_size) {
    // identify inputs by element count (metadata order: x, coord, W, a)
    const float *x = nullptr, *coord = nullptr, *W = nullptr, *a = nullptr;
    for (int i = 0; i < n_in; i++) {
        switch (in_sizes[i]) {
            case BB * NN * FIN: x     = (const float*)d_in[i]; break;
            case BB * NN * 3:   coord = (const float*)d_in[i]; break;
            case FIN * FOUT:    W     = (const float*)d_in[i]; break;
            case 2 * FOUT:      a     = (const float*)d_in[i]; break;
            default: break;
        }
    }
    float* out = (float*)d_out;

    gemm_h_kernel<<<(BB * NN) / 64, 256>>>(x, W, a);

    const int smem = (KT * FOUT + QT * PSS + KT * 4 + KT) * (int)sizeof(float);
    static bool attr_set = false;
    if (!attr_set) {
        cudaFuncSetAttribute(attn_kernel,
                             cudaFuncAttributeMaxDynamicSharedMemorySize, smem);
        attr_set = true;
    }
    attn_kernel<<<BB * (NN / QT), 256, smem>>>(coord, out);
}